// round 1
// baseline (speedup 1.0000x reference)
#include <cuda_runtime.h>
#include <math_constants.h>

#define D_K     128
#define D_MODEL 1024
#define SEQ     4096
#define BATCH   2
#define M_TOTAL (BATCH * SEQ)   // 8192

// Scratch for projected Q, K, V: [8192, 128] f32 each (4 MB each).
__device__ float g_q[M_TOTAL * D_K];
__device__ float g_k[M_TOTAL * D_K];
__device__ float g_v[M_TOTAL * D_K];

// ---------------------------------------------------------------------------
// Projection GEMM: out[m][n] = sum_k x[m][k] * w[k][n]
// M=8192, N=128, K=1024.  BM=64, BN=128, BK=16, 256 threads, micro-tile 4x8.
// gridDim = (128, 1, 3): z selects (wq->g_q, wk->g_k, wv->g_v).
// ---------------------------------------------------------------------------
__global__ __launch_bounds__(256) void proj_kernel(
    const float* __restrict__ x,
    const float* __restrict__ wq,
    const float* __restrict__ wk,
    const float* __restrict__ wv)
{
    __shared__ float Xs[64][17];    // padded: conflict-free column reads
    __shared__ float Ws[16][128];

    const float* w  = (blockIdx.z == 0) ? wq  : (blockIdx.z == 1) ? wk  : wv;
    float*       out = (blockIdx.z == 0) ? g_q : (blockIdx.z == 1) ? g_k : g_v;

    const int m0  = blockIdx.x * 64;
    const int tid = threadIdx.x;
    const int tx  = tid & 15;        // col group: cols tx*8 .. tx*8+7
    const int ty  = tid >> 4;        // row group: rows ty*4 .. ty*4+3

    // loader indices
    const int xr = tid >> 2;          // 0..63
    const int xc = (tid & 3) * 4;     // 0,4,8,12
    const int wr = tid >> 4;          // 0..15
    const int wc = (tid & 15) * 8;    // 0..120

    float acc[4][8];
    #pragma unroll
    for (int i = 0; i < 4; i++)
        #pragma unroll
        for (int j = 0; j < 8; j++) acc[i][j] = 0.0f;

    for (int k0 = 0; k0 < D_MODEL; k0 += 16) {
        // load X tile 64x16
        float4 xv = *(const float4*)(x + (size_t)(m0 + xr) * D_MODEL + k0 + xc);
        Xs[xr][xc + 0] = xv.x; Xs[xr][xc + 1] = xv.y;
        Xs[xr][xc + 2] = xv.z; Xs[xr][xc + 3] = xv.w;
        // load W tile 16x128
        *(float4*)(&Ws[wr][wc])     = *(const float4*)(w + (size_t)(k0 + wr) * D_K + wc);
        *(float4*)(&Ws[wr][wc + 4]) = *(const float4*)(w + (size_t)(k0 + wr) * D_K + wc + 4);
        __syncthreads();

        #pragma unroll
        for (int kk = 0; kk < 16; kk++) {
            float a[4];
            #pragma unroll
            for (int i = 0; i < 4; i++) a[i] = Xs[ty * 4 + i][kk];
            float4 b0 = *(const float4*)(&Ws[kk][tx * 8]);
            float4 b1 = *(const float4*)(&Ws[kk][tx * 8 + 4]);
            #pragma unroll
            for (int i = 0; i < 4; i++) {
                acc[i][0] += a[i] * b0.x; acc[i][1] += a[i] * b0.y;
                acc[i][2] += a[i] * b0.z; acc[i][3] += a[i] * b0.w;
                acc[i][4] += a[i] * b1.x; acc[i][5] += a[i] * b1.y;
                acc[i][6] += a[i] * b1.z; acc[i][7] += a[i] * b1.w;
            }
        }
        __syncthreads();
    }

    #pragma unroll
    for (int i = 0; i < 4; i++) {
        float* orow = out + (size_t)(m0 + ty * 4 + i) * D_K + tx * 8;
        float4 r0 = make_float4(acc[i][0], acc[i][1], acc[i][2], acc[i][3]);
        float4 r1 = make_float4(acc[i][4], acc[i][5], acc[i][6], acc[i][7]);
        *(float4*)(orow)     = r0;
        *(float4*)(orow + 4) = r1;
    }
}

// ---------------------------------------------------------------------------
// Flash attention with online softmax.
// Br=64 queries per block, 256 threads: thread = (q_local, quad),
// quad owns a 32-dim slice of the 128-dim head. Bc=32 K/V rows in smem.
// grid = (SEQ/Br, BATCH).
// ---------------------------------------------------------------------------
#define BR 64
#define BC 32

__global__ __launch_bounds__(256) void attn_kernel(float* __restrict__ out)
{
    __shared__ float Ks[BC][D_K];   // 16 KB
    __shared__ float Vs[BC][D_K];   // 16 KB

    const int b    = blockIdx.y;
    const int q0   = blockIdx.x * BR;
    const int tid  = threadIdx.x;
    const int quad = tid & 3;       // 32-dim slice
    const int ql   = tid >> 2;      // 0..63
    const int qrow = q0 + ql;

    const float scale = 0.08838834764831845f;   // 1/sqrt(128)

    // load my query slice into registers (8 x float4 = 32 floats)
    const float* qbase = g_q + ((size_t)b * SEQ + qrow) * D_K + quad * 32;
    float4 qr[8];
    #pragma unroll
    for (int i = 0; i < 8; i++) qr[i] = *(const float4*)(qbase + i * 4);

    float4 o[8];
    #pragma unroll
    for (int i = 0; i < 8; i++) o[i] = make_float4(0.f, 0.f, 0.f, 0.f);
    float m = -CUDART_INF_F;
    float l = 0.0f;

    const float* kb = g_k + (size_t)b * SEQ * D_K;
    const float* vb = g_v + (size_t)b * SEQ * D_K;

    for (int c0 = 0; c0 < SEQ; c0 += BC) {
        __syncthreads();
        // cooperative load of K,V tiles: BC*D_K = 4096 floats = 1024 float4 each
        #pragma unroll
        for (int i = 0; i < 4; i++) {
            int idx  = tid + i * 256;      // float4 index 0..1023
            int row  = idx >> 5;           // 32 float4 per row
            int col4 = idx & 31;
            ((float4*)Ks[row])[col4] = ((const float4*)(kb + (size_t)(c0 + row) * D_K))[col4];
            ((float4*)Vs[row])[col4] = ((const float4*)(vb + (size_t)(c0 + row) * D_K))[col4];
        }
        __syncthreads();

        // scores for this key block
        float s[BC];
        #pragma unroll
        for (int j = 0; j < BC; j++) {
            const float4* krow = (const float4*)(&Ks[j][quad * 32]);
            float4 a4 = make_float4(0.f, 0.f, 0.f, 0.f);
            #pragma unroll
            for (int i = 0; i < 8; i++) {
                float4 kv = krow[i];
                a4.x += qr[i].x * kv.x;
                a4.y += qr[i].y * kv.y;
                a4.z += qr[i].z * kv.z;
                a4.w += qr[i].w * kv.w;
            }
            float sj = (a4.x + a4.y) + (a4.z + a4.w);
            sj += __shfl_xor_sync(0xffffffffu, sj, 1);
            sj += __shfl_xor_sync(0xffffffffu, sj, 2);
            s[j] = sj * scale;
        }

        // block max + single rescale
        float mb = s[0];
        #pragma unroll
        for (int j = 1; j < BC; j++) mb = fmaxf(mb, s[j]);
        float m_new = fmaxf(m, mb);
        float alpha = __expf(m - m_new);   // exp(-inf)=0 on first block
        m = m_new;
        l *= alpha;
        #pragma unroll
        for (int i = 0; i < 8; i++) {
            o[i].x *= alpha; o[i].y *= alpha; o[i].z *= alpha; o[i].w *= alpha;
        }

        // accumulate P @ V
        #pragma unroll
        for (int j = 0; j < BC; j++) {
            float p = __expf(s[j] - m_new);
            l += p;
            const float4* vrow = (const float4*)(&Vs[j][quad * 32]);
            #pragma unroll
            for (int i = 0; i < 8; i++) {
                float4 vv = vrow[i];
                o[i].x += p * vv.x;
                o[i].y += p * vv.y;
                o[i].z += p * vv.z;
                o[i].w += p * vv.w;
            }
        }
    }

    const float inv = 1.0f / l;
    float* ob = out + ((size_t)b * SEQ + qrow) * D_K + quad * 32;
    #pragma unroll
    for (int i = 0; i < 8; i++) {
        float4 r = o[i];
        r.x *= inv; r.y *= inv; r.z *= inv; r.w *= inv;
        *(float4*)(ob + i * 4) = r;
    }
}

// ---------------------------------------------------------------------------
extern "C" void kernel_launch(void* const* d_in, const int* in_sizes, int n_in,
                              void* d_out, int out_size)
{
    const float* x  = (const float*)d_in[0];
    const float* wq = (const float*)d_in[1];
    const float* wk = (const float*)d_in[2];
    const float* wv = (const float*)d_in[3];
    float* out = (float*)d_out;

    (void)in_sizes; (void)n_in; (void)out_size;

    proj_kernel<<<dim3(M_TOTAL / 64, 1, 3), 256>>>(x, wq, wk, wv);
    attn_kernel<<<dim3(SEQ / BR, BATCH), 256>>>(out);
}

// round 3
// speedup vs baseline: 5.3788x; 5.3788x over previous
#include <cuda_runtime.h>
#include <math_constants.h>

#define D_K     128
#define D_MODEL 1024
#define SEQ     4096
#define BATCH   2
#define M_TOTAL (BATCH * SEQ)   // 8192

// Scratch for projected Q, K, V: [8192, 128] f32 each (4 MB each).
__device__ float g_q[M_TOTAL * D_K];
__device__ float g_k[M_TOTAL * D_K];
__device__ float g_v[M_TOTAL * D_K];

// ---------------------------------------------------------------------------
// Projection GEMM: out[m][n] = sum_k x[m][k] * w[k][n]
// M=8192, N=128, K=1024.  BM=64, BN=128, BK=16, 256 threads, micro-tile 4x8.
// ---------------------------------------------------------------------------
__global__ __launch_bounds__(256) void proj_kernel(
    const float* __restrict__ x,
    const float* __restrict__ wq,
    const float* __restrict__ wk,
    const float* __restrict__ wv)
{
    __shared__ float Xs[64][17];
    __shared__ float Ws[16][128];

    const float* w   = (blockIdx.z == 0) ? wq  : (blockIdx.z == 1) ? wk  : wv;
    float*       out = (blockIdx.z == 0) ? g_q : (blockIdx.z == 1) ? g_k : g_v;

    const int m0  = blockIdx.x * 64;
    const int tid = threadIdx.x;
    const int tx  = tid & 15;
    const int ty  = tid >> 4;

    const int xr = tid >> 2;
    const int xc = (tid & 3) * 4;
    const int wr = tid >> 4;
    const int wc = (tid & 15) * 8;

    float acc[4][8];
    #pragma unroll
    for (int i = 0; i < 4; i++)
        #pragma unroll
        for (int j = 0; j < 8; j++) acc[i][j] = 0.0f;

    for (int k0 = 0; k0 < D_MODEL; k0 += 16) {
        float4 xv = *(const float4*)(x + (size_t)(m0 + xr) * D_MODEL + k0 + xc);
        Xs[xr][xc + 0] = xv.x; Xs[xr][xc + 1] = xv.y;
        Xs[xr][xc + 2] = xv.z; Xs[xr][xc + 3] = xv.w;
        *(float4*)(&Ws[wr][wc])     = *(const float4*)(w + (size_t)(k0 + wr) * D_K + wc);
        *(float4*)(&Ws[wr][wc + 4]) = *(const float4*)(w + (size_t)(k0 + wr) * D_K + wc + 4);
        __syncthreads();

        #pragma unroll
        for (int kk = 0; kk < 16; kk++) {
            float a[4];
            #pragma unroll
            for (int i = 0; i < 4; i++) a[i] = Xs[ty * 4 + i][kk];
            float4 b0 = *(const float4*)(&Ws[kk][tx * 8]);
            float4 b1 = *(const float4*)(&Ws[kk][tx * 8 + 4]);
            #pragma unroll
            for (int i = 0; i < 4; i++) {
                acc[i][0] += a[i] * b0.x; acc[i][1] += a[i] * b0.y;
                acc[i][2] += a[i] * b0.z; acc[i][3] += a[i] * b0.w;
                acc[i][4] += a[i] * b1.x; acc[i][5] += a[i] * b1.y;
                acc[i][6] += a[i] * b1.z; acc[i][7] += a[i] * b1.w;
            }
        }
        __syncthreads();
    }

    #pragma unroll
    for (int i = 0; i < 4; i++) {
        float* orow = out + (size_t)(m0 + ty * 4 + i) * D_K + tx * 8;
        *(float4*)(orow)     = make_float4(acc[i][0], acc[i][1], acc[i][2], acc[i][3]);
        *(float4*)(orow + 4) = make_float4(acc[i][4], acc[i][5], acc[i][6], acc[i][7]);
    }
}

// ---------------------------------------------------------------------------
// Flash attention v2: two-GEMM structure, register micro-tiles.
// BR=64 queries/block, BC=128 keys/tile, 256 threads = 16x16 grid.
// Thread (ty,tx): QK frag 4q x 8k (k cols = tx+16u), PV frag 4q x 8d (d = tx+16u).
// Q,K stored d-major in smem (transposed on load); V row-major; P via smem.
// ---------------------------------------------------------------------------
#define BR 64
#define BC 128
#define QP 72    // Qs pitch (floats)
#define KP 136   // Ks pitch
#define VP 128   // Vs pitch
#define PP 132   // Ps pitch — BC=128 keys + 4 pad (R2 fix: was 68, overflow)
#define RP 17    // reduction pitch

#define SMEM_FLOATS (128*QP + 128*KP + BC*VP + BR*PP + BR*RP + 4*BR)
#define SMEM_BYTES  (SMEM_FLOATS * 4)

__global__ __launch_bounds__(256, 1) void attn2_kernel(float* __restrict__ out)
{
    extern __shared__ float sm[];
    float* Qs   = sm;                 // [128][QP]  d-major
    float* Ks   = Qs + 128 * QP;      // [128][KP]  d-major
    float* Vs   = Ks + 128 * KP;      // [BC][VP]   row-major
    float* Ps   = Vs + BC * VP;       // [BR][PP]
    float* red  = Ps + BR * PP;       // [BR][RP]
    float* m_s  = red + BR * RP;
    float* l_s  = m_s + BR;
    float* al_s = l_s + BR;
    float* mn_s = al_s + BR;

    const int b   = blockIdx.y;
    const int q0  = blockIdx.x * BR;
    const int tid = threadIdx.x;
    const int tx  = tid & 15;
    const int ty  = tid >> 4;

    const float scale = 0.08838834764831845f;  // 1/sqrt(128)

    if (tid < BR) { m_s[tid] = -CUDART_INF_F; l_s[tid] = 0.0f; }

    // Load Q tile transposed: Qs[d][q]
    {
        const float* qb = g_q + ((size_t)b * SEQ + q0) * D_K;
        const int j  = tid & 63;
        const int dg = tid >> 6;      // 0..3
        #pragma unroll
        for (int it = 0; it < 8; it++) {
            int d4 = dg * 8 + it;
            float4 v = *(const float4*)(qb + (size_t)j * D_K + d4 * 4);
            Qs[(4 * d4 + 0) * QP + j] = v.x;
            Qs[(4 * d4 + 1) * QP + j] = v.y;
            Qs[(4 * d4 + 2) * QP + j] = v.z;
            Qs[(4 * d4 + 3) * QP + j] = v.w;
        }
    }

    float O[4][8];
    #pragma unroll
    for (int i = 0; i < 4; i++)
        #pragma unroll
        for (int u = 0; u < 8; u++) O[i][u] = 0.0f;

    const float* kb = g_k + (size_t)b * SEQ * D_K;
    const float* vb = g_v + (size_t)b * SEQ * D_K;

    for (int c0 = 0; c0 < SEQ; c0 += BC) {
        __syncthreads();   // prev tile's Ks/Vs/Ps fully consumed

        // Load K tile transposed: Ks[d][k]
        {
            const int j  = tid & 127;
            const int dg = tid >> 7;  // 0..1
            #pragma unroll
            for (int it = 0; it < 16; it++) {
                int d4 = dg * 16 + it;
                float4 v = *(const float4*)(kb + (size_t)(c0 + j) * D_K + d4 * 4);
                Ks[(4 * d4 + 0) * KP + j] = v.x;
                Ks[(4 * d4 + 1) * KP + j] = v.y;
                Ks[(4 * d4 + 2) * KP + j] = v.z;
                Ks[(4 * d4 + 3) * KP + j] = v.w;
            }
        }
        // Load V tile row-major
        #pragma unroll
        for (int it = 0; it < 16; it++) {
            int idx = tid + it * 256;        // float4 index, 0..4095
            int row = idx >> 5;
            int c4  = idx & 31;
            *(float4*)(Vs + row * VP + c4 * 4) =
                *(const float4*)(vb + (size_t)(c0 + row) * D_K + c4 * 4);
        }
        __syncthreads();

        // ---- S = Q @ K^T ----
        float s[4][8];
        #pragma unroll
        for (int i = 0; i < 4; i++)
            #pragma unroll
            for (int u = 0; u < 8; u++) s[i][u] = 0.0f;

        #pragma unroll 8
        for (int kk = 0; kk < 128; kk++) {
            float4 a = *(const float4*)(Qs + kk * QP + ty * 4);
            float bb[8];
            #pragma unroll
            for (int u = 0; u < 8; u++) bb[u] = Ks[kk * KP + tx + 16 * u];
            #pragma unroll
            for (int u = 0; u < 8; u++) {
                s[0][u] += a.x * bb[u];
                s[1][u] += a.y * bb[u];
                s[2][u] += a.z * bb[u];
                s[3][u] += a.w * bb[u];
            }
        }

        // scale + per-thread partial row max
        #pragma unroll
        for (int i = 0; i < 4; i++) {
            float pm = -CUDART_INF_F;
            #pragma unroll
            for (int u = 0; u < 8; u++) {
                s[i][u] *= scale;
                pm = fmaxf(pm, s[i][u]);
            }
            red[(ty * 4 + i) * RP + tx] = pm;
        }
        __syncthreads();

        if (tid < BR) {
            float rm = red[tid * RP];
            #pragma unroll
            for (int t = 1; t < 16; t++) rm = fmaxf(rm, red[tid * RP + t]);
            float mo = m_s[tid];
            float mn = fmaxf(mo, rm);
            float al = __expf(mo - mn);   // 0 on first tile
            m_s[tid]  = mn;
            mn_s[tid] = mn;
            al_s[tid] = al;
            l_s[tid] *= al;
        }
        __syncthreads();

        // p = exp(s - m), write P, partial row sums, rescale O
        #pragma unroll
        for (int i = 0; i < 4; i++) {
            int q = ty * 4 + i;
            float mn = mn_s[q];
            float al = al_s[q];
            float ps = 0.0f;
            #pragma unroll
            for (int u = 0; u < 8; u++) {
                float p = __expf(s[i][u] - mn);
                Ps[q * PP + tx + 16 * u] = p;
                ps += p;
                O[i][u] *= al;
            }
            red[q * RP + tx] = ps;
        }
        __syncthreads();

        if (tid < BR) {
            float ssum = 0.0f;
            #pragma unroll
            for (int t = 0; t < 16; t++) ssum += red[tid * RP + t];
            l_s[tid] += ssum;
        }

        // ---- O += P @ V ----
        #pragma unroll 8
        for (int k = 0; k < BC; k++) {
            float p[4];
            #pragma unroll
            for (int i = 0; i < 4; i++) p[i] = Ps[(ty * 4 + i) * PP + k];
            #pragma unroll
            for (int u = 0; u < 8; u++) {
                float v = Vs[k * VP + tx + 16 * u];
                #pragma unroll
                for (int i = 0; i < 4; i++) O[i][u] += p[i] * v;
            }
        }
    }

    __syncthreads();   // final l_s visible
    #pragma unroll
    for (int i = 0; i < 4; i++) {
        int q = ty * 4 + i;
        float inv = 1.0f / l_s[q];
        float* ob = out + ((size_t)b * SEQ + q0 + q) * D_K;
        #pragma unroll
        for (int u = 0; u < 8; u++) ob[tx + 16 * u] = O[i][u] * inv;
    }
}

// ---------------------------------------------------------------------------
extern "C" void kernel_launch(void* const* d_in, const int* in_sizes, int n_in,
                              void* d_out, int out_size)
{
    const float* x  = (const float*)d_in[0];
    const float* wq = (const float*)d_in[1];
    const float* wk = (const float*)d_in[2];
    const float* wv = (const float*)d_in[3];
    float* out = (float*)d_out;

    (void)in_sizes; (void)n_in; (void)out_size;

    cudaFuncSetAttribute(attn2_kernel,
                         cudaFuncAttributeMaxDynamicSharedMemorySize, SMEM_BYTES);

    proj_kernel<<<dim3(M_TOTAL / 64, 1, 3), 256>>>(x, wq, wk, wv);
    attn2_kernel<<<dim3(SEQ / BR, BATCH), 256, SMEM_BYTES>>>(out);
}